// round 7
// baseline (speedup 1.0000x reference)
#include <cuda_runtime.h>

#define BS    64
#define NC    80
#define NA    8400
#define TOPK  13
#define EPSF  1e-9f

#define ATHR  1024
#define ELEM  9            // ceil(NA / ATHR)
#define NWARP (ATHR / 32)

#define PB_ANCH 132        // phase-B anchors per block: 64*132 = 8448 >= 8400

// norm_align_metric scratch (float bits). Zeroed at load; phase B resets its
// own slice after reading, so it's zeroed again before every next call.
__device__ unsigned int d_norm_bits[NA];
// Monotone arrival counter for the single-wave grid sync (never reset; each
// call consumes exactly 64 tickets, so target = (old & ~63) + 64).
__device__ unsigned int d_arrive;

static __device__ __forceinline__ unsigned long long u64max(unsigned long long a,
                                                            unsigned long long b) {
    return a > b ? a : b;
}

// Fused kernel: 64 blocks (one per batch row), 1024 threads, single wave.
// Phase A: align metric -> exact top-13 -> mask row + norm atomicMax.
// Grid sync (ticket counter).
// Phase B: each block writes a 132-anchor slab of target_scores and resets
// its d_norm_bits slice.
__global__ __launch_bounds__(ATHR, 1) void taa_fused(
    const float* __restrict__ pd_scores,   // (BS, NC, NA)
    const float* __restrict__ pd_bboxes,   // (BS, 4, NA)
    const int*   __restrict__ gt_labels,   // (BS,)
    const float* __restrict__ gt_bboxes,   // (BS, 4)
    float*       __restrict__ target_out,  // (NA, BS)
    float*       __restrict__ mask_out)    // (BS, NA)
{
    __shared__ unsigned long long s_cand[TOPK * NWARP];  // [k*32 + warp]
    __shared__ unsigned long long s_top[TOPK];
    __shared__ float s_topv[TOPK];
    __shared__ int   s_topi[TOPK];
    __shared__ float s_iou[TOPK];
    __shared__ float s_ratio;
    __shared__ float s_lab[BS];

    const int b    = blockIdx.x;
    const int tid  = threadIdx.x;
    const int lane = tid & 31;
    const int wid  = tid >> 5;

    // Labels for phase B (load early, independent of everything else).
    if (tid < BS) s_lab[tid] = (float)gt_labels[tid];

    const float gx1 = gt_bboxes[b * 4 + 0];
    const float gy1 = gt_bboxes[b * 4 + 1];
    const float gx2 = gt_bboxes[b * 4 + 2];
    const float gy2 = gt_bboxes[b * 4 + 3];
    const float area1 = fmaxf(gx2 - gx1, 0.f) * fmaxf(gy2 - gy1, 0.f);
    const int   label = gt_labels[b];

    const float* __restrict__ px1 = pd_bboxes + ((long)b * 4 + 0) * NA;
    const float* __restrict__ py1 = pd_bboxes + ((long)b * 4 + 1) * NA;
    const float* __restrict__ px2 = pd_bboxes + ((long)b * 4 + 2) * NA;
    const float* __restrict__ py2 = pd_bboxes + ((long)b * 4 + 3) * NA;
    const float* __restrict__ sc  = pd_scores + ((long)b * NC + label) * NA;
    float* __restrict__ mrow = mask_out + (long)b * NA;

    // ---- Phase A.1: align metric -> packed u64 register candidates.
    // pack = (float_bits(align) << 32) | (0xFFFFFFFF - anchor):
    // u64 max == (higher align, then lower anchor), matching top_k stability.
    unsigned long long p[ELEM];
    #pragma unroll
    for (int i = 0; i < ELEM; i++) {
        int a = i * ATHR + tid;
        if (a < NA) {
            float bx1 = px1[a], by1 = py1[a], bx2 = px2[a], by2 = py2[a];
            float iw = fmaxf(fminf(gx2, bx2) - fmaxf(gx1, bx1), 0.f);
            float ih = fmaxf(fminf(gy2, by2) - fmaxf(gy1, by1), 0.f);
            float ov = iw * ih;
            float a2 = fmaxf(bx2 - bx1, 0.f) * fmaxf(by2 - by1, 0.f);
            float iou = ov / (area1 + a2 - ov + EPSF);
            float iou2 = iou * iou;
            float align = sc[a] * (iou2 * iou2 * iou2);
            p[i] = ((unsigned long long)__float_as_uint(align) << 32)
                 | (unsigned long long)(0xFFFFFFFFu - (unsigned)a);
            mrow[a] = 0.0f;
        } else {
            p[i] = 0ull;
        }
    }

    // ---- Phase A.2 stage 1: per-warp top-13, butterfly shuffles, no barriers.
    #pragma unroll
    for (int k = 0; k < TOPK; k++) {
        unsigned long long m = 0ull;
        #pragma unroll
        for (int i = 0; i < ELEM; i++) m = u64max(m, p[i]);
        #pragma unroll
        for (int o = 16; o > 0; o >>= 1)
            m = u64max(m, __shfl_xor_sync(0xFFFFFFFFu, m, o));
        if (lane == 0) s_cand[k * NWARP + wid] = m;
        #pragma unroll
        for (int i = 0; i < ELEM; i++) if (p[i] == m) p[i] = 0ull;
    }
    __syncthreads();

    // ---- Phase A.2 stage 2: warp 0 merges 32*13 = 416 candidates.
    if (wid == 0) {
        unsigned long long q[TOPK];
        #pragma unroll
        for (int j = 0; j < TOPK; j++) q[j] = s_cand[j * NWARP + lane];
        #pragma unroll
        for (int k = 0; k < TOPK; k++) {
            unsigned long long m = 0ull;
            #pragma unroll
            for (int j = 0; j < TOPK; j++) m = u64max(m, q[j]);
            #pragma unroll
            for (int o = 16; o > 0; o >>= 1)
                m = u64max(m, __shfl_xor_sync(0xFFFFFFFFu, m, o));
            if (lane == 0) s_top[k] = m;
            #pragma unroll
            for (int j = 0; j < TOPK; j++) if (q[j] == m) q[j] = 0ull;
        }
    }
    __syncthreads();

    // ---- Phase A.3: decode winners, recompute raw IoU (pos_overlaps).
    if (tid < TOPK) {
        unsigned long long w = s_top[tid];
        float v = __uint_as_float((unsigned)(w >> 32));
        int   a = (int)(0xFFFFFFFFu - (unsigned)(w & 0xFFFFFFFFull));
        s_topv[tid] = v;
        s_topi[tid] = a;
        float bx1 = px1[a], by1 = py1[a], bx2 = px2[a], by2 = py2[a];
        float iw = fmaxf(fminf(gx2, bx2) - fmaxf(gx1, bx1), 0.f);
        float ih = fmaxf(fminf(gy2, by2) - fmaxf(gy1, by1), 0.f);
        float ov = iw * ih;
        float a2 = fmaxf(bx2 - bx1, 0.f) * fmaxf(by2 - by1, 0.f);
        s_iou[tid] = ov / (area1 + a2 - ov + EPSF);
    }
    __syncthreads();

    if (tid == 0) {
        float po = 0.f;
        #pragma unroll
        for (int k = 0; k < TOPK; k++) po = fmaxf(po, s_iou[k]);
        s_ratio = po / (s_topv[0] + EPSF);   // pos_overlaps / (pos_align + eps)
    }
    __syncthreads();

    if (s_topv[0] > EPSF && tid < TOPK) {
        int a = s_topi[tid];
        mrow[a] = 1.0f;
        float contrib = s_topv[tid] * s_ratio;
        atomicMax(&d_norm_bits[a], __float_as_uint(contrib));
    }
    // invalid row: mask all-zero (cnt>1 collapse), no norm contribution.

    // ---- Grid sync: single-wave ticket barrier (monotone, replay-safe).
    __syncthreads();
    if (tid == 0) {
        __threadfence();
        unsigned old = atomicAdd(&d_arrive, 1u);
        unsigned tgt = (old & ~63u) + 64u;
        while (*(volatile unsigned*)&d_arrive < tgt) { }
        __threadfence();
    }
    __syncthreads();

    // ---- Phase B: target_scores[a, j] = lab[j] * norm[a], (NA, BS) layout.
    const int a0 = b * PB_ANCH;
    const int nA = (a0 + PB_ANCH <= NA) ? PB_ANCH : (NA - a0);
    const int la = tid >> 4;            // 0..63: local anchor within iteration
    const int j4 = (tid & 15) << 2;     // 0,4,...,60: column group

    #pragma unroll
    for (int it = 0; it < 3; it++) {    // 3*64 = 192 >= 132 anchors
        int al = it * 64 + la;
        if (al < nA) {
            int a = a0 + al;
            float nv = __uint_as_float(d_norm_bits[a]);
            float4 v = make_float4(nv * s_lab[j4 + 0], nv * s_lab[j4 + 1],
                                   nv * s_lab[j4 + 2], nv * s_lab[j4 + 3]);
            *reinterpret_cast<float4*>(target_out + (long)a * BS + j4) = v;
        }
    }
    __syncthreads();
    // Reset own slice (sole reader of this range) for the next call.
    if (tid < nA) d_norm_bits[a0 + tid] = 0u;
}

extern "C" void kernel_launch(void* const* d_in, const int* in_sizes, int n_in,
                              void* d_out, int out_size) {
    const float* pd_scores = (const float*)d_in[0];
    const float* pd_bboxes = (const float*)d_in[1];
    const int*   gt_labels = (const int*)d_in[2];
    const float* gt_bboxes = (const float*)d_in[3];

    float* target = (float*)d_out;                       // (NA, BS)
    float* mask   = (float*)d_out + (size_t)NA * BS;     // (BS, NA)

    taa_fused<<<BS, ATHR>>>(pd_scores, pd_bboxes, gt_labels, gt_bboxes,
                            target, mask);
}